// round 14
// baseline (speedup 1.0000x reference)
#include <cuda_runtime.h>
#include <cuda_bf16.h>
#include <cstdint>
#include <math.h>

// ---------------- problem constants ----------------
#define F_IN  128
#define D1    128
#define N_CLS 64
#define MAXN  50000
#define MAXE  800000
#define SCAN_CHUNK 4096
#define MAXB ((MAXN + SCAN_CHUNK - 1) / SCAN_CHUNK)
#define LDA 136   // padded smem row pitch in bf16 (272 B)
#define W_ELEMS (128 * 128 + 64 * 128)   // 24576

// ---------------- device scratch ----------------
__device__ float g_h1[MAXN * D1];
__device__ float g_a1[MAXN * D1];
__device__ float g_h2[MAXN * N_CLS];
__device__ int   g_deg[MAXN];
__device__ float g_dis[MAXN];
__device__ int   g_rowptr[MAXN + 1];
__device__ int   g_cursor[MAXN];
__device__ int2  g_edge[MAXE];                 // (src, norm-bits)
__device__ unsigned long long g_state[MAXB];   // lookback: flag<<32 | value
// bf16-split transposed weights, plain [N][128] row-major
__device__ __nv_bfloat16 g_w1h[128 * 128];
__device__ __nv_bfloat16 g_w1l[128 * 128];
__device__ __nv_bfloat16 g_w2h[64 * 128];
__device__ __nv_bfloat16 g_w2l[64 * 128];

// ---------------- helpers ----------------
__device__ __forceinline__ uint32_t smem_u32(const void* p) {
    uint32_t a;
    asm("{ .reg .u64 t; cvta.to.shared.u64 t, %1; cvt.u32.u64 %0, t; }" : "=r"(a) : "l"(p));
    return a;
}
// x4: lanes 0-15 address the hi plane, lanes 16-31 the lo plane (merged load)
__device__ __forceinline__ void ldmatrix_x4(uint32_t& r0, uint32_t& r1, uint32_t& r2,
                                            uint32_t& r3, uint32_t addr) {
    asm volatile("ldmatrix.sync.aligned.m8n8.x4.shared.b16 {%0,%1,%2,%3}, [%4];"
                 : "=r"(r0), "=r"(r1), "=r"(r2), "=r"(r3) : "r"(addr));
}
__device__ __forceinline__ void mma_bf16(float* c, const uint32_t* a, uint32_t b0, uint32_t b1) {
    asm volatile("mma.sync.aligned.m16n8k16.row.col.f32.bf16.bf16.f32 "
                 "{%0,%1,%2,%3}, {%4,%5,%6,%7}, {%8,%9}, {%0,%1,%2,%3};"
                 : "+f"(c[0]), "+f"(c[1]), "+f"(c[2]), "+f"(c[3])
                 : "r"(a[0]), "r"(a[1]), "r"(a[2]), "r"(a[3]), "r"(b0), "r"(b1));
}
__device__ __forceinline__ uint32_t pack_bf16x2(__nv_bfloat16 lo, __nv_bfloat16 hi) {
    return ((uint32_t)__bfloat16_as_ushort(hi) << 16) | (uint32_t)__bfloat16_as_ushort(lo);
}
// split a float2 into hi-bf16x2 and lo-bf16x2 (residual)
__device__ __forceinline__ void split2(float2 f, uint32_t& h, uint32_t& l) {
    __nv_bfloat16 hx = __float2bfloat16(f.x), hy = __float2bfloat16(f.y);
    h = pack_bf16x2(hx, hy);
    l = pack_bf16x2(__float2bfloat16(f.x - __bfloat162float(hx)),
                    __float2bfloat16(f.y - __bfloat162float(hy)));
}

// ---------------- fused prep: weight split/transpose + degree count + state zero ----------------
__global__ void k_prep(const float* __restrict__ W1, const float* __restrict__ W2,
                       const int* __restrict__ dst, int E, int n) {
    int idx = blockIdx.x * blockDim.x + threadIdx.x;
    if (idx < MAXB) g_state[idx] = 0ull;
    if (idx < 128 * 128) {
        int nn = idx >> 7, k = idx & 127;
        float w = W1[k * 128 + nn];
        __nv_bfloat16 h = __float2bfloat16(w);
        g_w1h[idx] = h;
        g_w1l[idx] = __float2bfloat16(w - __bfloat162float(h));
    } else if (idx < W_ELEMS) {
        int j = idx - 16384;
        int nn = j >> 7, k = j & 127;
        float w = W2[k * 64 + nn];
        __nv_bfloat16 h = __float2bfloat16(w);
        g_w2h[j] = h;
        g_w2l[j] = __float2bfloat16(w - __bfloat162float(h));
    } else {
        int e = idx - W_ELEMS;
        if (e < E) {
            int d = dst[e];
            if ((unsigned)d < (unsigned)n) atomicAdd(&g_deg[d], 1);
        }
    }
}

// ---------------- single-pass decoupled-lookback scan ----------------
__global__ void __launch_bounds__(1024) k_scan(int n, int nb) {
    __shared__ int wsum[32];
    __shared__ int carry_s;
    int tid = threadIdx.x, lane = tid & 31, wid = tid >> 5;
    int bid = blockIdx.x;
    int base = bid * SCAN_CHUNK + tid * 4;

    int v[4];
    #pragma unroll
    for (int j = 0; j < 4; j++) {
        int i = base + j;
        int raw = (i < n) ? g_deg[i] : 0;
        v[j] = raw;
        if (i < n) g_dis[i] = rsqrtf((float)(raw + 1));
    }
    int tsum = v[0] + v[1] + v[2] + v[3];
    int x = tsum;
    #pragma unroll
    for (int off = 1; off < 32; off <<= 1) {
        int y = __shfl_up_sync(0xffffffffu, x, off);
        if (lane >= off) x += y;
    }
    if (lane == 31) wsum[wid] = x;
    __syncthreads();
    if (wid == 0) {
        int w = wsum[lane];
        #pragma unroll
        for (int off = 1; off < 32; off <<= 1) {
            int y = __shfl_up_sync(0xffffffffu, w, off);
            if (lane >= off) w += y;
        }
        wsum[lane] = w;
    }
    __syncthreads();
    int total = wsum[31];
    int excl = (wid ? wsum[wid - 1] : 0) + (x - tsum);

    if (tid == 0) {
        if (bid == 0) {
            atomicExch(&g_state[0], (2ull << 32) | (unsigned long long)(unsigned)total);
            carry_s = 0;
        } else {
            atomicExch(&g_state[bid], (1ull << 32) | (unsigned long long)(unsigned)total);
            int carry = 0;
            for (int j = bid - 1; j >= 0; j--) {
                unsigned long long s;
                do { s = atomicAdd(&g_state[j], 0ull); } while ((s >> 32) == 0ull);
                carry += (int)(unsigned)s;
                if ((s >> 32) == 2ull) break;
            }
            atomicExch(&g_state[bid], (2ull << 32) | (unsigned long long)(unsigned)(total + carry));
            carry_s = carry;
        }
    }
    __syncthreads();

    int e = excl + carry_s;
    #pragma unroll
    for (int j = 0; j < 4; j++) {
        int i = base + j;
        if (i < n) { g_rowptr[i] = e; g_cursor[i] = e; }
        e += v[j];
    }
    if (bid == nb - 1 && tid == 1023) g_rowptr[n] = carry_s + total;
}

// ---------------- scatter (packed src+norm) ----------------
__global__ void k_scatter(const int* __restrict__ src,
                          const int* __restrict__ dst, int E, int n) {
    int e = blockIdx.x * blockDim.x + threadIdx.x;
    if (e >= E) return;
    int s = src[e];
    int d = dst[e];
    if ((unsigned)s >= (unsigned)n || (unsigned)d >= (unsigned)n) return;
    int pos = atomicAdd(&g_cursor[d], 1);
    g_edge[pos] = make_int2(s, __float_as_int(g_dis[s] * g_dis[d]));
}

// ---------------- HMMA GEMM: C[M,N] = A[M,128] @ Wt[N,128]^T, bf16 split ----------------
// block = 256 threads (8 warps), M-tile 128; A fragments loaded directly from
// gmem (no A smem). B hi+lo fragments fetched with ONE merged ldmatrix.x4:
// lanes 0-15 address sBh, lanes 16-31 address sBl.
template <int N>
__global__ void __launch_bounds__(256, 2) k_gemm_tc(const float* __restrict__ A,
                                                    const __nv_bfloat16* __restrict__ Bh,
                                                    const __nv_bfloat16* __restrict__ Bl,
                                                    float* __restrict__ C, int M) {
    constexpr int NT = N / 8;
    constexpr int B_ELE = N * LDA;
    extern __shared__ __nv_bfloat16 sm[];
    __nv_bfloat16* sBh = sm;
    __nv_bfloat16* sBl = sm + B_ELE;

    int tid = threadIdx.x, wid = tid >> 5, lane = tid & 31;
    int row0 = blockIdx.x * 128;

    // stage B (16 uint4 = 128 bf16 per row)
    {
        const uint4* bh = (const uint4*)Bh;
        const uint4* bl = (const uint4*)Bl;
        for (int i = tid; i < N * 16; i += 256) {
            int r = i >> 4, c = i & 15;
            int d = r * LDA + c * 8;
            *(uint4*)(sBh + d) = bh[i];
            *(uint4*)(sBl + d) = bl[i];
        }
    }
    __syncthreads();

    // A direct-load lane mapping (m16n8k16 row-major A fragment)
    int g = lane >> 2;            // 0..7
    int c0 = (lane & 3) * 2;      // 0,2,4,6
    int r0 = row0 + wid * 16 + g;
    int r1 = r0 + 8;
    bool v0 = r0 < M, v1 = r1 < M;
    const float* a0p = A + (size_t)(v0 ? r0 : 0) * 128;
    const float* a1p = A + (size_t)(v1 ? r1 : 0) * 128;

    // merged B address: lanes 0-15 -> hi plane, lanes 16-31 -> lo plane
    uint32_t bOff = (uint32_t)(lane & 7) * (LDA * 2) + (uint32_t)((lane >> 3) & 1) * 16;
    uint32_t b_base = smem_u32((lane & 16) ? sBl : sBh) + bOff;

    float acc[NT][4];
    #pragma unroll
    for (int t = 0; t < NT; t++) { acc[t][0] = acc[t][1] = acc[t][2] = acc[t][3] = 0.f; }

    const float2 f2z = make_float2(0.f, 0.f);
    #pragma unroll
    for (int kk = 0; kk < 8; kk++) {
        int k0 = kk * 16 + c0;
        float2 f00 = v0 ? *(const float2*)(a0p + k0)     : f2z;
        float2 f10 = v1 ? *(const float2*)(a1p + k0)     : f2z;
        float2 f01 = v0 ? *(const float2*)(a0p + k0 + 8) : f2z;
        float2 f11 = v1 ? *(const float2*)(a1p + k0 + 8) : f2z;
        uint32_t ah[4], al[4];
        split2(f00, ah[0], al[0]);
        split2(f10, ah[1], al[1]);
        split2(f01, ah[2], al[2]);
        split2(f11, ah[3], al[3]);
        #pragma unroll
        for (int t = 0; t < NT; t++) {
            uint32_t bh0, bh1, bl0, bl1;
            uint32_t boff = (uint32_t)t * 8 * (LDA * 2) + kk * 32;
            ldmatrix_x4(bh0, bh1, bl0, bl1, b_base + boff);
            mma_bf16(acc[t], ah, bh0, bh1);   // Ah*Bh
            mma_bf16(acc[t], ah, bl0, bl1);   // Ah*Bl
            mma_bf16(acc[t], al, bh0, bh1);   // Al*Bh
        }
    }

    int tig = lane & 3;
    #pragma unroll
    for (int t = 0; t < NT; t++) {
        int col = t * 8 + tig * 2;
        if (v0) *(float2*)(C + (size_t)r0 * N + col) = make_float2(acc[t][0], acc[t][1]);
        if (v1) *(float2*)(C + (size_t)r1 * N + col) = make_float2(acc[t][2], acc[t][3]);
    }
}

// ---------------- aggregation: warp/node, 128 features ----------------
template <bool RELU>
__global__ void k_agg128(const float* __restrict__ h,
                         const float* __restrict__ bias,
                         float* __restrict__ out, int n) {
    int gwarp = (blockIdx.x * blockDim.x + threadIdx.x) >> 5;
    if (gwarp >= n) return;
    int lane = threadIdx.x & 31;
    const float4* hv = (const float4*)h;
    float d = g_dis[gwarp];
    float4 v = hv[gwarp * 32 + lane];
    float sn = d * d;
    float4 acc = make_float4(sn * v.x, sn * v.y, sn * v.z, sn * v.w);
    int e = g_rowptr[gwarp], e1 = g_rowptr[gwarp + 1];
    for (; e + 4 <= e1; e += 4) {
        int2 q0 = g_edge[e + 0], q1 = g_edge[e + 1], q2 = g_edge[e + 2], q3 = g_edge[e + 3];
        float n0 = __int_as_float(q0.y), n1 = __int_as_float(q1.y);
        float n2 = __int_as_float(q2.y), n3 = __int_as_float(q3.y);
        float4 v0 = hv[q0.x * 32 + lane];
        float4 v1 = hv[q1.x * 32 + lane];
        float4 v2 = hv[q2.x * 32 + lane];
        float4 v3 = hv[q3.x * 32 + lane];
        acc.x += n0 * v0.x + n1 * v1.x + n2 * v2.x + n3 * v3.x;
        acc.y += n0 * v0.y + n1 * v1.y + n2 * v2.y + n3 * v3.y;
        acc.z += n0 * v0.z + n1 * v1.z + n2 * v2.z + n3 * v3.z;
        acc.w += n0 * v0.w + n1 * v1.w + n2 * v2.w + n3 * v3.w;
    }
    for (; e < e1; e++) {
        int2 q = g_edge[e];
        float nm = __int_as_float(q.y);
        float4 vv = hv[q.x * 32 + lane];
        acc.x += nm * vv.x; acc.y += nm * vv.y;
        acc.z += nm * vv.z; acc.w += nm * vv.w;
    }
    float4 b = ((const float4*)bias)[lane];
    acc.x += b.x; acc.y += b.y; acc.z += b.z; acc.w += b.w;
    if (RELU) {
        acc.x = fmaxf(acc.x, 0.f); acc.y = fmaxf(acc.y, 0.f);
        acc.z = fmaxf(acc.z, 0.f); acc.w = fmaxf(acc.w, 0.f);
    }
    ((float4*)out)[gwarp * 32 + lane] = acc;
}

// ---------------- aggregation: warp/node, 64 features ----------------
template <bool RELU>
__global__ void k_agg64(const float* __restrict__ h,
                        const float* __restrict__ bias,
                        float* __restrict__ out, int n) {
    int gwarp = (blockIdx.x * blockDim.x + threadIdx.x) >> 5;
    if (gwarp >= n) return;
    int lane = threadIdx.x & 31;
    const float2* hv = (const float2*)h;
    float d = g_dis[gwarp];
    float2 v = hv[gwarp * 32 + lane];
    float sn = d * d;
    float2 acc = make_float2(sn * v.x, sn * v.y);
    int e = g_rowptr[gwarp], e1 = g_rowptr[gwarp + 1];
    for (; e + 4 <= e1; e += 4) {
        int2 q0 = g_edge[e + 0], q1 = g_edge[e + 1], q2 = g_edge[e + 2], q3 = g_edge[e + 3];
        float n0 = __int_as_float(q0.y), n1 = __int_as_float(q1.y);
        float n2 = __int_as_float(q2.y), n3 = __int_as_float(q3.y);
        float2 v0 = hv[q0.x * 32 + lane];
        float2 v1 = hv[q1.x * 32 + lane];
        float2 v2 = hv[q2.x * 32 + lane];
        float2 v3 = hv[q3.x * 32 + lane];
        acc.x += n0 * v0.x + n1 * v1.x + n2 * v2.x + n3 * v3.x;
        acc.y += n0 * v0.y + n1 * v1.y + n2 * v2.y + n3 * v3.y;
    }
    for (; e < e1; e++) {
        int2 q = g_edge[e];
        float nm = __int_as_float(q.y);
        float2 vv = hv[q.x * 32 + lane];
        acc.x += nm * vv.x; acc.y += nm * vv.y;
    }
    float2 b = ((const float2*)bias)[lane];
    acc.x += b.x; acc.y += b.y;
    if (RELU) { acc.x = fmaxf(acc.x, 0.f); acc.y = fmaxf(acc.y, 0.f); }
    ((float2*)out)[gwarp * 32 + lane] = acc;
}

// ---------------- launch ----------------
extern "C" void kernel_launch(void* const* d_in, const int* in_sizes, int n_in,
                              void* d_out, int out_size) {
    const float* x    = (const float*)d_in[0];
    const int*   eidx = (const int*)d_in[1];
    const float* W1   = (const float*)d_in[2];
    const float* b1   = (const float*)d_in[3];
    const float* W2   = (const float*)d_in[4];
    const float* b2   = (const float*)d_in[5];
    float*       out  = (float*)d_out;

    int n = in_sizes[0] / F_IN;
    int E = in_sizes[1] / 2;
    const int* src = eidx;
    const int* dst = eidx + E;
    int nb = (n + SCAN_CHUNK - 1) / SCAN_CHUNK;

    const int SMEM1 = 2 * 128 * LDA * 2;   // 69632 B (B hi+lo only)
    const int SMEM2 = 2 * 64 * LDA * 2;    // 34816 B
    cudaFuncSetAttribute(k_gemm_tc<128>, cudaFuncAttributeMaxDynamicSharedMemorySize, SMEM1);
    cudaFuncSetAttribute(k_gemm_tc<64>,  cudaFuncAttributeMaxDynamicSharedMemorySize, SMEM2);

    float* h1;  cudaGetSymbolAddress((void**)&h1, g_h1);
    float* a1;  cudaGetSymbolAddress((void**)&a1, g_a1);
    float* h2;  cudaGetSymbolAddress((void**)&h2, g_h2);
    int* degp;  cudaGetSymbolAddress((void**)&degp, g_deg);
    __nv_bfloat16 *w1h, *w1l, *w2h, *w2l;
    cudaGetSymbolAddress((void**)&w1h, g_w1h);
    cudaGetSymbolAddress((void**)&w1l, g_w1l);
    cudaGetSymbolAddress((void**)&w2h, g_w2h);
    cudaGetSymbolAddress((void**)&w2l, g_w2l);

    // graph structure build (3 kernels + 1 memset)
    cudaMemsetAsync(degp, 0, (size_t)n * sizeof(int), 0);
    k_prep<<<(W_ELEMS + E + 255) / 256, 256>>>(W1, W2, dst, E, n);
    k_scan<<<nb, 1024>>>(n, nb);
    k_scatter<<<(E + 255) / 256, 256>>>(src, dst, E, n);

    int aggBlocks = (n + 7) / 8;
    int gemmBlocks = (n + 127) / 128;

    // layer 1
    k_gemm_tc<128><<<gemmBlocks, 256, SMEM1>>>(x, w1h, w1l, h1, n);
    k_agg128<true><<<aggBlocks, 256>>>(h1, b1, a1, n);
    // layer 2
    k_gemm_tc<64><<<gemmBlocks, 256, SMEM2>>>(a1, w2h, w2l, h2, n);
    k_agg64<false><<<aggBlocks, 256>>>(h2, b2, out, n);
}

// round 15
// speedup vs baseline: 1.1609x; 1.1609x over previous
#include <cuda_runtime.h>
#include <cuda_bf16.h>
#include <cuda_fp16.h>
#include <cstdint>
#include <math.h>

// ---------------- problem constants ----------------
#define F_IN  128
#define D1    128
#define N_CLS 64
#define MAXN  50000
#define MAXE  800000
#define SCAN_CHUNK 4096
#define MAXB ((MAXN + SCAN_CHUNK - 1) / SCAN_CHUNK)
#define LDA 136   // padded smem row pitch in bf16 (272 B)
#define W_ELEMS (128 * 128 + 64 * 128)   // 24576

// ---------------- device scratch ----------------
__device__ __half g_h1[MAXN * D1];      // x @ W1  (fp16: gathered by agg128)
__device__ float  g_a1[MAXN * D1];      // relu(agg(h1)+b1)  (fp32: streamed by GEMM2)
__device__ __half g_h2[MAXN * N_CLS];   // a1 @ W2 (fp16: gathered by agg64)
__device__ int    g_deg[MAXN];
__device__ float  g_dis[MAXN];
__device__ int    g_rowptr[MAXN + 1];
__device__ int    g_cursor[MAXN];
__device__ int2   g_edge[MAXE];                 // (src, norm-bits)
__device__ unsigned long long g_state[MAXB];    // lookback: flag<<32 | value
// bf16-split transposed weights, plain [N][128] row-major
__device__ __nv_bfloat16 g_w1h[128 * 128];
__device__ __nv_bfloat16 g_w1l[128 * 128];
__device__ __nv_bfloat16 g_w2h[64 * 128];
__device__ __nv_bfloat16 g_w2l[64 * 128];

// ---------------- helpers ----------------
__device__ __forceinline__ uint32_t smem_u32(const void* p) {
    uint32_t a;
    asm("{ .reg .u64 t; cvta.to.shared.u64 t, %1; cvt.u32.u64 %0, t; }" : "=r"(a) : "l"(p));
    return a;
}
__device__ __forceinline__ void ldmatrix_x2(uint32_t& r0, uint32_t& r1, uint32_t addr) {
    asm volatile("ldmatrix.sync.aligned.m8n8.x2.shared.b16 {%0,%1}, [%2];"
                 : "=r"(r0), "=r"(r1) : "r"(addr));
}
__device__ __forceinline__ void mma_bf16(float* c, const uint32_t* a, uint32_t b0, uint32_t b1) {
    asm volatile("mma.sync.aligned.m16n8k16.row.col.f32.bf16.bf16.f32 "
                 "{%0,%1,%2,%3}, {%4,%5,%6,%7}, {%8,%9}, {%0,%1,%2,%3};"
                 : "+f"(c[0]), "+f"(c[1]), "+f"(c[2]), "+f"(c[3])
                 : "r"(a[0]), "r"(a[1]), "r"(a[2]), "r"(a[3]), "r"(b0), "r"(b1));
}
__device__ __forceinline__ uint32_t pack_bf16x2(__nv_bfloat16 lo, __nv_bfloat16 hi) {
    return ((uint32_t)__bfloat16_as_ushort(hi) << 16) | (uint32_t)__bfloat16_as_ushort(lo);
}
// split a float2 into hi-bf16x2 and lo-bf16x2 (residual)
__device__ __forceinline__ void split2(float2 f, uint32_t& h, uint32_t& l) {
    __nv_bfloat16 hx = __float2bfloat16(f.x), hy = __float2bfloat16(f.y);
    h = pack_bf16x2(hx, hy);
    l = pack_bf16x2(__float2bfloat16(f.x - __bfloat162float(hx)),
                    __float2bfloat16(f.y - __bfloat162float(hy)));
}

// ---------------- fused prep: weight split/transpose + degree count + state zero ----------------
__global__ void k_prep(const float* __restrict__ W1, const float* __restrict__ W2,
                       const int* __restrict__ dst, int E, int n) {
    int idx = blockIdx.x * blockDim.x + threadIdx.x;
    if (idx < MAXB) g_state[idx] = 0ull;
    if (idx < 128 * 128) {
        int nn = idx >> 7, k = idx & 127;
        float w = W1[k * 128 + nn];
        __nv_bfloat16 h = __float2bfloat16(w);
        g_w1h[idx] = h;
        g_w1l[idx] = __float2bfloat16(w - __bfloat162float(h));
    } else if (idx < W_ELEMS) {
        int j = idx - 16384;
        int nn = j >> 7, k = j & 127;
        float w = W2[k * 64 + nn];
        __nv_bfloat16 h = __float2bfloat16(w);
        g_w2h[j] = h;
        g_w2l[j] = __float2bfloat16(w - __bfloat162float(h));
    } else {
        int e = idx - W_ELEMS;
        if (e < E) {
            int d = dst[e];
            if ((unsigned)d < (unsigned)n) atomicAdd(&g_deg[d], 1);
        }
    }
}

// ---------------- single-pass decoupled-lookback scan ----------------
__global__ void __launch_bounds__(1024) k_scan(int n, int nb) {
    __shared__ int wsum[32];
    __shared__ int carry_s;
    int tid = threadIdx.x, lane = tid & 31, wid = tid >> 5;
    int bid = blockIdx.x;
    int base = bid * SCAN_CHUNK + tid * 4;

    int v[4];
    #pragma unroll
    for (int j = 0; j < 4; j++) {
        int i = base + j;
        int raw = (i < n) ? g_deg[i] : 0;
        v[j] = raw;
        if (i < n) g_dis[i] = rsqrtf((float)(raw + 1));
    }
    int tsum = v[0] + v[1] + v[2] + v[3];
    int x = tsum;
    #pragma unroll
    for (int off = 1; off < 32; off <<= 1) {
        int y = __shfl_up_sync(0xffffffffu, x, off);
        if (lane >= off) x += y;
    }
    if (lane == 31) wsum[wid] = x;
    __syncthreads();
    if (wid == 0) {
        int w = wsum[lane];
        #pragma unroll
        for (int off = 1; off < 32; off <<= 1) {
            int y = __shfl_up_sync(0xffffffffu, w, off);
            if (lane >= off) w += y;
        }
        wsum[lane] = w;
    }
    __syncthreads();
    int total = wsum[31];
    int excl = (wid ? wsum[wid - 1] : 0) + (x - tsum);

    if (tid == 0) {
        if (bid == 0) {
            atomicExch(&g_state[0], (2ull << 32) | (unsigned long long)(unsigned)total);
            carry_s = 0;
        } else {
            atomicExch(&g_state[bid], (1ull << 32) | (unsigned long long)(unsigned)total);
            int carry = 0;
            for (int j = bid - 1; j >= 0; j--) {
                unsigned long long s;
                do { s = atomicAdd(&g_state[j], 0ull); } while ((s >> 32) == 0ull);
                carry += (int)(unsigned)s;
                if ((s >> 32) == 2ull) break;
            }
            atomicExch(&g_state[bid], (2ull << 32) | (unsigned long long)(unsigned)(total + carry));
            carry_s = carry;
        }
    }
    __syncthreads();

    int e = excl + carry_s;
    #pragma unroll
    for (int j = 0; j < 4; j++) {
        int i = base + j;
        if (i < n) { g_rowptr[i] = e; g_cursor[i] = e; }
        e += v[j];
    }
    if (bid == nb - 1 && tid == 1023) g_rowptr[n] = carry_s + total;
}

// ---------------- scatter (packed src+norm) ----------------
__global__ void k_scatter(const int* __restrict__ src,
                          const int* __restrict__ dst, int E, int n) {
    int e = blockIdx.x * blockDim.x + threadIdx.x;
    if (e >= E) return;
    int s = src[e];
    int d = dst[e];
    if ((unsigned)s >= (unsigned)n || (unsigned)d >= (unsigned)n) return;
    int pos = atomicAdd(&g_cursor[d], 1);
    g_edge[pos] = make_int2(s, __float_as_int(g_dis[s] * g_dis[d]));
}

// ---------------- HMMA GEMM: C[M,N](fp16) = A[M,128](fp32) @ Wt[N,128]^T, bf16 split ----------
// block = 256 threads (8 warps), M-tile 128; A fragments loaded directly from
// gmem (no A smem), B hi/lo planes via two ldmatrix.x2 (R13 proven form).
template <int N>
__global__ void __launch_bounds__(256, 2) k_gemm_tc(const float* __restrict__ A,
                                                    const __nv_bfloat16* __restrict__ Bh,
                                                    const __nv_bfloat16* __restrict__ Bl,
                                                    __half* __restrict__ C, int M) {
    constexpr int NT = N / 8;
    constexpr int B_ELE = N * LDA;
    extern __shared__ __nv_bfloat16 sm[];
    __nv_bfloat16* sBh = sm;
    __nv_bfloat16* sBl = sm + B_ELE;

    int tid = threadIdx.x, wid = tid >> 5, lane = tid & 31;
    int row0 = blockIdx.x * 128;

    // stage B (16 uint4 = 128 bf16 per row)
    {
        const uint4* bh = (const uint4*)Bh;
        const uint4* bl = (const uint4*)Bl;
        for (int i = tid; i < N * 16; i += 256) {
            int r = i >> 4, c = i & 15;
            int d = r * LDA + c * 8;
            *(uint4*)(sBh + d) = bh[i];
            *(uint4*)(sBl + d) = bl[i];
        }
    }
    __syncthreads();

    // A direct-load lane mapping (m16n8k16 row-major A fragment)
    int g = lane >> 2;            // 0..7
    int c0 = (lane & 3) * 2;      // 0,2,4,6
    int r0 = row0 + wid * 16 + g;
    int r1 = r0 + 8;
    bool v0 = r0 < M, v1 = r1 < M;
    const float* a0p = A + (size_t)(v0 ? r0 : 0) * 128;
    const float* a1p = A + (size_t)(v1 ? r1 : 0) * 128;

    uint32_t bOff = (uint32_t)(lane & 7) * (LDA * 2) + (uint32_t)((lane >> 3) & 1) * 16;
    uint32_t bh_base = smem_u32(sBh) + bOff;
    uint32_t bl_base = smem_u32(sBl) + bOff;

    float acc[NT][4];
    #pragma unroll
    for (int t = 0; t < NT; t++) { acc[t][0] = acc[t][1] = acc[t][2] = acc[t][3] = 0.f; }

    const float2 f2z = make_float2(0.f, 0.f);
    #pragma unroll
    for (int kk = 0; kk < 8; kk++) {
        int k0 = kk * 16 + c0;
        float2 f00 = v0 ? *(const float2*)(a0p + k0)     : f2z;
        float2 f10 = v1 ? *(const float2*)(a1p + k0)     : f2z;
        float2 f01 = v0 ? *(const float2*)(a0p + k0 + 8) : f2z;
        float2 f11 = v1 ? *(const float2*)(a1p + k0 + 8) : f2z;
        uint32_t ah[4], al[4];
        split2(f00, ah[0], al[0]);
        split2(f10, ah[1], al[1]);
        split2(f01, ah[2], al[2]);
        split2(f11, ah[3], al[3]);
        #pragma unroll
        for (int t = 0; t < NT; t++) {
            uint32_t b0, b1, d0, d1;
            uint32_t boff = (uint32_t)t * 8 * (LDA * 2) + kk * 32;
            ldmatrix_x2(b0, b1, bh_base + boff);
            ldmatrix_x2(d0, d1, bl_base + boff);
            mma_bf16(acc[t], ah, b0, b1);   // Ah*Bh
            mma_bf16(acc[t], ah, d0, d1);   // Ah*Bl
            mma_bf16(acc[t], al, b0, b1);   // Al*Bh
        }
    }

    int tig = lane & 3;
    #pragma unroll
    for (int t = 0; t < NT; t++) {
        int col = t * 8 + tig * 2;
        if (v0) *(__half2*)(C + (size_t)r0 * N + col) = __floats2half2_rn(acc[t][0], acc[t][1]);
        if (v1) *(__half2*)(C + (size_t)r1 * N + col) = __floats2half2_rn(acc[t][2], acc[t][3]);
    }
}

// ---------------- aggregation: warp/node, 128 features, fp16 gather ----------------
template <bool RELU>
__global__ void k_agg128(const __half* __restrict__ h,
                         const float* __restrict__ bias,
                         float* __restrict__ out, int n) {
    int gwarp = (blockIdx.x * blockDim.x + threadIdx.x) >> 5;
    if (gwarp >= n) return;
    int lane = threadIdx.x & 31;
    const uint2* hv = (const uint2*)h;    // 4 halves per uint2; 32 lanes = 128 feats
    float d = g_dis[gwarp];
    float sn = d * d;

    uint2 qs = hv[(size_t)gwarp * 32 + lane];
    float2 s0 = __half22float2(*(__half2*)&qs.x);
    float2 s1 = __half22float2(*(__half2*)&qs.y);
    float4 acc = make_float4(sn * s0.x, sn * s0.y, sn * s1.x, sn * s1.y);

    int e = g_rowptr[gwarp], e1 = g_rowptr[gwarp + 1];
    for (; e + 4 <= e1; e += 4) {
        int2 q0 = g_edge[e + 0], q1 = g_edge[e + 1], q2 = g_edge[e + 2], q3 = g_edge[e + 3];
        float n0 = __int_as_float(q0.y), n1 = __int_as_float(q1.y);
        float n2 = __int_as_float(q2.y), n3 = __int_as_float(q3.y);
        uint2 w0 = hv[(size_t)q0.x * 32 + lane];
        uint2 w1 = hv[(size_t)q1.x * 32 + lane];
        uint2 w2 = hv[(size_t)q2.x * 32 + lane];
        uint2 w3 = hv[(size_t)q3.x * 32 + lane];
        float2 a0 = __half22float2(*(__half2*)&w0.x), b0 = __half22float2(*(__half2*)&w0.y);
        float2 a1 = __half22float2(*(__half2*)&w1.x), b1 = __half22float2(*(__half2*)&w1.y);
        float2 a2 = __half22float2(*(__half2*)&w2.x), b2 = __half22float2(*(__half2*)&w2.y);
        float2 a3 = __half22float2(*(__half2*)&w3.x), b3 = __half22float2(*(__half2*)&w3.y);
        acc.x += n0 * a0.x + n1 * a1.x + n2 * a2.x + n3 * a3.x;
        acc.y += n0 * a0.y + n1 * a1.y + n2 * a2.y + n3 * a3.y;
        acc.z += n0 * b0.x + n1 * b1.x + n2 * b2.x + n3 * b3.x;
        acc.w += n0 * b0.y + n1 * b1.y + n2 * b2.y + n3 * b3.y;
    }
    for (; e < e1; e++) {
        int2 q = g_edge[e];
        float nm = __int_as_float(q.y);
        uint2 w = hv[(size_t)q.x * 32 + lane];
        float2 a = __half22float2(*(__half2*)&w.x), b = __half22float2(*(__half2*)&w.y);
        acc.x += nm * a.x; acc.y += nm * a.y;
        acc.z += nm * b.x; acc.w += nm * b.y;
    }
    float4 b = ((const float4*)bias)[lane];
    acc.x += b.x; acc.y += b.y; acc.z += b.z; acc.w += b.w;
    if (RELU) {
        acc.x = fmaxf(acc.x, 0.f); acc.y = fmaxf(acc.y, 0.f);
        acc.z = fmaxf(acc.z, 0.f); acc.w = fmaxf(acc.w, 0.f);
    }
    ((float4*)out)[(size_t)gwarp * 32 + lane] = acc;
}

// ---------------- aggregation: warp/node, 64 features, fp16 gather ----------------
template <bool RELU>
__global__ void k_agg64(const __half* __restrict__ h,
                        const float* __restrict__ bias,
                        float* __restrict__ out, int n) {
    int gwarp = (blockIdx.x * blockDim.x + threadIdx.x) >> 5;
    if (gwarp >= n) return;
    int lane = threadIdx.x & 31;
    const uint32_t* hv = (const uint32_t*)h;   // 2 halves per uint32; 32 lanes = 64 feats
    float d = g_dis[gwarp];
    float sn = d * d;

    float2 s = __half22float2(*(__half2*)&hv[(size_t)gwarp * 32 + lane]);
    float2 acc = make_float2(sn * s.x, sn * s.y);

    int e = g_rowptr[gwarp], e1 = g_rowptr[gwarp + 1];
    for (; e + 4 <= e1; e += 4) {
        int2 q0 = g_edge[e + 0], q1 = g_edge[e + 1], q2 = g_edge[e + 2], q3 = g_edge[e + 3];
        float n0 = __int_as_float(q0.y), n1 = __int_as_float(q1.y);
        float n2 = __int_as_float(q2.y), n3 = __int_as_float(q3.y);
        uint32_t w0 = hv[(size_t)q0.x * 32 + lane];
        uint32_t w1 = hv[(size_t)q1.x * 32 + lane];
        uint32_t w2 = hv[(size_t)q2.x * 32 + lane];
        uint32_t w3 = hv[(size_t)q3.x * 32 + lane];
        float2 a0 = __half22float2(*(__half2*)&w0);
        float2 a1 = __half22float2(*(__half2*)&w1);
        float2 a2 = __half22float2(*(__half2*)&w2);
        float2 a3 = __half22float2(*(__half2*)&w3);
        acc.x += n0 * a0.x + n1 * a1.x + n2 * a2.x + n3 * a3.x;
        acc.y += n0 * a0.y + n1 * a1.y + n2 * a2.y + n3 * a3.y;
    }
    for (; e < e1; e++) {
        int2 q = g_edge[e];
        float nm = __int_as_float(q.y);
        float2 a = __half22float2(*(__half2*)&hv[(size_t)q.x * 32 + lane]);
        acc.x += nm * a.x; acc.y += nm * a.y;
    }
    float2 b = ((const float2*)bias)[lane];
    acc.x += b.x; acc.y += b.y;
    if (RELU) { acc.x = fmaxf(acc.x, 0.f); acc.y = fmaxf(acc.y, 0.f); }
    ((float2*)out)[(size_t)gwarp * 32 + lane] = acc;
}

// ---------------- launch ----------------
extern "C" void kernel_launch(void* const* d_in, const int* in_sizes, int n_in,
                              void* d_out, int out_size) {
    const float* x    = (const float*)d_in[0];
    const int*   eidx = (const int*)d_in[1];
    const float* W1   = (const float*)d_in[2];
    const float* b1   = (const float*)d_in[3];
    const float* W2   = (const float*)d_in[4];
    const float* b2   = (const float*)d_in[5];
    float*       out  = (float*)d_out;

    int n = in_sizes[0] / F_IN;
    int E = in_sizes[1] / 2;
    const int* src = eidx;
    const int* dst = eidx + E;
    int nb = (n + SCAN_CHUNK - 1) / SCAN_CHUNK;

    const int SMEM1 = 2 * 128 * LDA * 2;   // 69632 B (B hi+lo only)
    const int SMEM2 = 2 * 64 * LDA * 2;    // 34816 B
    cudaFuncSetAttribute(k_gemm_tc<128>, cudaFuncAttributeMaxDynamicSharedMemorySize, SMEM1);
    cudaFuncSetAttribute(k_gemm_tc<64>,  cudaFuncAttributeMaxDynamicSharedMemorySize, SMEM2);

    __half* h1; cudaGetSymbolAddress((void**)&h1, g_h1);
    float*  a1; cudaGetSymbolAddress((void**)&a1, g_a1);
    __half* h2; cudaGetSymbolAddress((void**)&h2, g_h2);
    int*  degp; cudaGetSymbolAddress((void**)&degp, g_deg);
    __nv_bfloat16 *w1h, *w1l, *w2h, *w2l;
    cudaGetSymbolAddress((void**)&w1h, g_w1h);
    cudaGetSymbolAddress((void**)&w1l, g_w1l);
    cudaGetSymbolAddress((void**)&w2h, g_w2h);
    cudaGetSymbolAddress((void**)&w2l, g_w2l);

    // graph structure build (3 kernels + 1 memset)
    cudaMemsetAsync(degp, 0, (size_t)n * sizeof(int), 0);
    k_prep<<<(W_ELEMS + E + 255) / 256, 256>>>(W1, W2, dst, E, n);
    k_scan<<<nb, 1024>>>(n, nb);
    k_scatter<<<(E + 255) / 256, 256>>>(src, dst, E, n);

    int aggBlocks = (n + 7) / 8;
    int gemmBlocks = (n + 127) / 128;

    // layer 1
    k_gemm_tc<128><<<gemmBlocks, 256, SMEM1>>>(x, w1h, w1l, h1, n);
    k_agg128<true><<<aggBlocks, 256>>>(h1, b1, a1, n);
    // layer 2
    k_gemm_tc<64><<<gemmBlocks, 256, SMEM2>>>(a1, w2h, w2l, h2, n);
    k_agg64<false><<<aggBlocks, 256>>>(h2, b2, out, n);
}